// round 3
// baseline (speedup 1.0000x reference)
#include <cuda_runtime.h>

// Problem constants
#define NROWS     8192
#define KDIM      1024
#define SHORTLIST 4000
#define C1HI      20000
#define NCLASSES  50257
#define HEADC     4002   // shortlist + 2 tail-cluster logits

// GEMM tile config
#define BM 64
#define BN 64
#define BK 16

// ---------------- scratch (device globals; no allocation allowed) ------------
__device__ float g_head_sum[NROWS];    // sum(exp(head logits)) per row
__device__ float g_tail_sum[NROWS];    // sum(exp(cluster logits)) per row (tail rows)
__device__ float g_head_gath[NROWS];   // head logit at gather index
__device__ float g_targ_logit[NROWS];  // full-table target logit (tail rows)
__device__ int   g_rows[2][NROWS];     // compacted row lists for clusters 1,2
__device__ int   g_cnt[2];
__device__ float g_loss;

__device__ __forceinline__ int cluster_of(int t) {
    return (t < SHORTLIST) ? 0 : ((t < C1HI) ? 1 : 2);
}

// ---------------- init: zero accumulators every launch -----------------------
__global__ void init_kernel() {
    int i = blockIdx.x * blockDim.x + threadIdx.x;
    if (i < NROWS) { g_head_sum[i] = 0.f; g_tail_sum[i] = 0.f; }
    if (i == 0) { g_cnt[0] = 0; g_cnt[1] = 0; g_loss = 0.f; }
}

// ---------------- compact rows by cluster ------------------------------------
__global__ void compact_kernel(const int* __restrict__ target) {
    int i = blockIdx.x * blockDim.x + threadIdx.x;
    if (i >= NROWS) return;
    int c = cluster_of(target[i]);
    if (c > 0) {
        int p = atomicAdd(&g_cnt[c - 1], 1);
        g_rows[c - 1][p] = i;
    }
}

// ---------------- fused GEMM + sum(exp) + gather ------------------------------
// mode 0: head (all rows, cols [0,4002): weight[0:4000] ++ tail_vectors)
// mode 1: cluster 1 rows, cols [4000,20000)
// mode 2: cluster 2 rows, cols [20000,50257)
__global__ __launch_bounds__(256)
void gemm_lse_kernel(const float* __restrict__ input,
                     const int*   __restrict__ target,
                     const float* __restrict__ weight,
                     const float* __restrict__ bias,
                     const float* __restrict__ tailv,
                     const float* __restrict__ tailb,
                     int mode)
{
    __shared__ float As[BK][BM + 4];
    __shared__ float Bs[BK][BN + 4];

    int nrows, collo, colhi;
    const int* rowlist;
    if (mode == 0)      { nrows = NROWS;    collo = 0;         colhi = HEADC;    rowlist = nullptr;   }
    else if (mode == 1) { nrows = g_cnt[0]; collo = SHORTLIST; colhi = C1HI;     rowlist = g_rows[0]; }
    else                { nrows = g_cnt[1]; collo = C1HI;      colhi = NCLASSES; rowlist = g_rows[1]; }

    const int by = blockIdx.x;   // row tile (fast axis -> weight tile L2 reuse)
    const int bx = blockIdx.y;   // col tile
    if (by * BM >= nrows) return;

    const int tid = threadIdx.x;
    const int lr = tid >> 2;     // 0..63: row within tile (for loads)
    const int lq = tid & 3;      // quad within K-slab

    // A (input) load pointer
    int growl = by * BM + lr;
    int arow  = (growl < nrows) ? (rowlist ? rowlist[growl] : growl) : 0;
    const float* aptr = input + (size_t)arow * KDIM + lq * 4;

    // B (weight row) load pointer
    int gcoll = collo + bx * BN + lr;
    int bcol  = (gcoll < colhi) ? gcoll : (colhi - 1);
    const float* brow;
    if (mode == 0 && bcol >= SHORTLIST) brow = tailv + (size_t)(bcol - SHORTLIST) * KDIM;
    else                                brow = weight + (size_t)bcol * KDIM;
    const float* bptr = brow + lq * 4;

    float acc[4][4] = {};
    const int ty = tid >> 4;     // 0..15 -> rows ty*4..ty*4+3
    const int tx = tid & 15;     // 0..15 -> cols tx*4..tx*4+3

    for (int k0 = 0; k0 < KDIM; k0 += BK) {
        float4 av = *(const float4*)(aptr + k0);
        float4 bv = *(const float4*)(bptr + k0);
        As[lq * 4 + 0][lr] = av.x; As[lq * 4 + 1][lr] = av.y;
        As[lq * 4 + 2][lr] = av.z; As[lq * 4 + 3][lr] = av.w;
        Bs[lq * 4 + 0][lr] = bv.x; Bs[lq * 4 + 1][lr] = bv.y;
        Bs[lq * 4 + 2][lr] = bv.z; Bs[lq * 4 + 3][lr] = bv.w;
        __syncthreads();
        #pragma unroll
        for (int k = 0; k < BK; k++) {
            float4 a = *(const float4*)&As[k][ty * 4];
            float4 b = *(const float4*)&Bs[k][tx * 4];
            acc[0][0] += a.x * b.x; acc[0][1] += a.x * b.y; acc[0][2] += a.x * b.z; acc[0][3] += a.x * b.w;
            acc[1][0] += a.y * b.x; acc[1][1] += a.y * b.y; acc[1][2] += a.y * b.z; acc[1][3] += a.y * b.w;
            acc[2][0] += a.z * b.x; acc[2][1] += a.z * b.y; acc[2][2] += a.z * b.z; acc[2][3] += a.z * b.w;
            acc[3][0] += a.w * b.x; acc[3][1] += a.w * b.y; acc[3][2] += a.w * b.z; acc[3][3] += a.w * b.w;
        }
        __syncthreads();
    }

    // Epilogue: add bias, sum exp per row, capture gathered logits.
    // Logits are small (|x| < ~5) so sum(exp) needs no max subtraction.
    #pragma unroll
    for (int i = 0; i < 4; i++) {
        int  grow   = by * BM + ty * 4 + i;
        bool rvalid = (grow < nrows);
        int  orow = 0, gidx = -1;
        if (rvalid) {
            orow = rowlist ? rowlist[grow] : grow;
            int tgt = target[orow];
            if (mode == 0) {
                int cid = cluster_of(tgt);
                gidx = (cid == 0) ? tgt : (SHORTLIST + cid - 1);
            } else {
                gidx = tgt;
            }
        }
        float s = 0.f;
        #pragma unroll
        for (int j = 0; j < 4; j++) {
            int gcol = collo + bx * BN + tx * 4 + j;
            if (gcol < colhi) {
                float bb = (mode == 0 && gcol >= SHORTLIST) ? tailb[gcol - SHORTLIST]
                                                            : bias[gcol];
                float logit = acc[i][j] + bb;
                s += __expf(logit);
                if (rvalid && gcol == gidx) {
                    if (mode == 0) g_head_gath[orow] = logit;
                    else           g_targ_logit[orow] = logit;
                }
            }
        }
        // reduce partial sums across the 16 lanes that share this row
        #pragma unroll
        for (int off = 8; off > 0; off >>= 1)
            s += __shfl_xor_sync(0xffffffffu, s, off, 16);
        if (tx == 0 && rvalid) {
            if (mode == 0) atomicAdd(&g_head_sum[orow], s);
            else           atomicAdd(&g_tail_sum[orow], s);
        }
    }
}

// ---------------- finalize: output[i] and loss partial sums -------------------
__global__ void finalize_kernel(const int* __restrict__ target,
                                float* __restrict__ out)
{
    __shared__ float red[256];
    int i = blockIdx.x * 256 + threadIdx.x;
    float neg = 0.f;
    if (i < NROWS) {
        int cid = cluster_of(target[i]);
        float res = g_head_gath[i] - logf(g_head_sum[i]);
        if (cid > 0) res += g_targ_logit[i] - logf(g_tail_sum[i]);
        out[i] = res;
        neg = -res;
    }
    red[threadIdx.x] = neg;
    __syncthreads();
    #pragma unroll
    for (int s2 = 128; s2 > 0; s2 >>= 1) {
        if (threadIdx.x < s2) red[threadIdx.x] += red[threadIdx.x + s2];
        __syncthreads();
    }
    if (threadIdx.x == 0) atomicAdd(&g_loss, red[0]);
}

__global__ void write_loss_kernel(float* __restrict__ out, int out_size) {
    if (out_size > NROWS) out[NROWS] = g_loss / (float)NROWS;
}

// ---------------- launch ------------------------------------------------------
extern "C" void kernel_launch(void* const* d_in, const int* in_sizes, int n_in,
                              void* d_out, int out_size) {
    const float* input  = (const float*)d_in[0];
    const int*   target = (const int*)  d_in[1];
    const float* weight = (const float*)d_in[2];
    const float* bias   = (const float*)d_in[3];
    const float* tailv  = (const float*)d_in[4];
    const float* tailb  = (const float*)d_in[5];
    float* out = (float*)d_out;

    init_kernel<<<NROWS / 256, 256>>>();
    compact_kernel<<<NROWS / 256, 256>>>(target);

    // head: all rows x 4002 cols
    dim3 gh(NROWS / BM, (HEADC + BN - 1) / BN);
    gemm_lse_kernel<<<gh, 256>>>(input, target, weight, bias, tailv, tailb, 0);
    // cluster 1: compacted rows x 16000 cols (row tiles early-exit past count)
    dim3 g1(NROWS / BM, (C1HI - SHORTLIST) / BN);
    gemm_lse_kernel<<<g1, 256>>>(input, target, weight, bias, tailv, tailb, 1);
    // cluster 2: compacted rows x 30257 cols
    dim3 g2(NROWS / BM, (NCLASSES - C1HI + BN - 1) / BN);
    gemm_lse_kernel<<<g2, 256>>>(input, target, weight, bias, tailv, tailb, 2);

    finalize_kernel<<<NROWS / 256, 256>>>(target, out);
    write_loss_kernel<<<1, 1>>>(out, out_size);
}

// round 6
// speedup vs baseline: 4.1764x; 4.1764x over previous
#include <cuda_runtime.h>
#include <cstdint>

// Problem constants
#define NROWS     8192
#define KDIM      1024
#define SHORTLIST 4000
#define C1HI      20000
#define NCLASSES  50257
#define HEADC     4002   // shortlist + 2 tail-cluster logits

// Tile config
#define TM 128            // CTA rows
#define TN 128            // CTA cols (classes)
#define NSTG 3            // cp.async stages, K=32 floats each
#define STAGE_BYTES (TM*128 + TN*128)          // 16KB A + 16KB B
// layout: [align slack ≤1024][NSTG stages][bias 512B]
#define SMEM_TOTAL  (1024 + NSTG*STAGE_BYTES + 512)

// ---------------- scratch ----------------------------------------------------
__device__ float g_head_sum[NROWS];
__device__ float g_tail_sum[NROWS];
__device__ float g_head_gath[NROWS];
__device__ float g_targ_logit[NROWS];
__device__ int   g_rows[2][NROWS];
__device__ int   g_cnt[2];
__device__ float g_loss;

__device__ __forceinline__ int cluster_of(int t) {
    return (t < SHORTLIST) ? 0 : ((t < C1HI) ? 1 : 2);
}

__device__ __forceinline__ uint32_t smem_u32(const void* p) {
    uint32_t a;
    asm("{ .reg .u64 t; cvta.to.shared.u64 t, %1; cvt.u32.u64 %0, t; }" : "=r"(a) : "l"(p));
    return a;
}
#define CP16(dst, src) \
    asm volatile("cp.async.cg.shared.global [%0], [%1], 16;" :: "r"(dst), "l"(src) : "memory")
#define CP_COMMIT() asm volatile("cp.async.commit_group;" ::: "memory")

// ldmatrix x4 .b16 — four 8x8 b16 (= 8x4 float) matrices; tf32 frag loader
#define LDSM4(r, a) \
    asm volatile("ldmatrix.sync.aligned.m8n8.x4.shared.b16 {%0,%1,%2,%3}, [%4];" \
                 : "=r"((r)[0]), "=r"((r)[1]), "=r"((r)[2]), "=r"((r)[3]) : "r"(a))

#define MMA_TF32(c, a, b0, b1) \
    asm volatile("mma.sync.aligned.m16n8k8.row.col.f32.tf32.tf32.f32 " \
                 "{%0,%1,%2,%3}, {%4,%5,%6,%7}, {%8,%9}, {%0,%1,%2,%3};" \
                 : "+f"((c)[0]), "+f"((c)[1]), "+f"((c)[2]), "+f"((c)[3]) \
                 : "r"((a)[0]), "r"((a)[1]), "r"((a)[2]), "r"((a)[3]), "r"(b0), "r"(b1))

// ---------------- init / compact ---------------------------------------------
__global__ void init_kernel() {
    int i = blockIdx.x * blockDim.x + threadIdx.x;
    if (i < NROWS) { g_head_sum[i] = 0.f; g_tail_sum[i] = 0.f; }
    if (i == 0) { g_cnt[0] = 0; g_cnt[1] = 0; g_loss = 0.f; }
}
__global__ void compact_kernel(const int* __restrict__ target) {
    int i = blockIdx.x * blockDim.x + threadIdx.x;
    if (i >= NROWS) return;
    int c = cluster_of(target[i]);
    if (c > 0) {
        int p = atomicAdd(&g_cnt[c - 1], 1);
        g_rows[c - 1][p] = i;
    }
}

// ---------------- fused tf32 tensor GEMM + sum(exp) + gather -----------------
// mode 0: head (all rows, cols [0,4002): weight[0:4000] ++ tail_vectors)
// mode 1: cluster-1 rows (compacted), cols [4000,20000)
// mode 2: cluster-2 rows (compacted), cols [20000,50257)
__global__ __launch_bounds__(256, 1)
void tc_gemm_lse(const float* __restrict__ input,
                 const int*   __restrict__ target,
                 const float* __restrict__ weight,
                 const float* __restrict__ bias,
                 const float* __restrict__ tailv,
                 const float* __restrict__ tailb,
                 int mode)
{
    extern __shared__ char smem[];

    int nrows, collo, colhi;
    const int* rowlist;
    if (mode == 0)      { nrows = NROWS;    collo = 0;         colhi = HEADC;    rowlist = nullptr;   }
    else if (mode == 1) { nrows = g_cnt[0]; collo = SHORTLIST; colhi = C1HI;     rowlist = g_rows[0]; }
    else                { nrows = g_cnt[1]; collo = C1HI;      colhi = NCLASSES; rowlist = g_rows[1]; }

    const int by = blockIdx.x;   // row tile (fast axis -> weight tile L2 reuse)
    const int bx = blockIdx.y;   // col tile
    if (by * TM >= nrows) return;

    const int tid = threadIdx.x;
    const int wid = tid >> 5;
    const int lid = tid & 31;
    const int wm  = wid >> 2;    // 0..1 -> rows wm*64..
    const int wn  = wid & 3;     // 0..3 -> cols wn*32..

    uint32_t sb     = smem_u32(smem);
    uint32_t stage0 = (sb + 1023) & ~1023u;
    // bias lives AFTER the stage buffers (round-5 bug: it aliased stage 0)
    float* bias_sm  = (float*)(smem + (stage0 - sb) + NSTG * STAGE_BYTES);

    // bias tile into smem
    if (tid < TN) {
        int gcol = collo + bx * TN + tid;
        float bb = 0.f;
        if (mode == 0) {
            if (gcol < SHORTLIST)  bb = bias[gcol];
            else if (gcol < HEADC) bb = tailb[gcol - SHORTLIST];
        } else if (gcol < colhi)   bb = bias[gcol];
        bias_sm[tid] = bb;
    }

    // ---- cp.async load plan: 8 x 16B chunks per thread per stage (4 A + 4 B)
    const float* asrc[4]; uint32_t adst[4];
    const float* bsrc[4]; uint32_t bdst[4];
    #pragma unroll
    for (int i = 0; i < 4; i++) {
        int id  = tid + i * 256;          // chunk id 0..1023
        int row = id >> 3, c = id & 7;    // row 0..127, chunk-in-row 0..7
        int grow = by * TM + row;
        int arow = (grow < nrows) ? (rowlist ? rowlist[grow] : grow) : 0;
        asrc[i]  = input + (size_t)arow * KDIM + c * 4;
        adst[i]  = row * 128 + ((c * 16) ^ ((row & 7) * 16));
        int gcol = collo + bx * TN + row;
        const float* bp;
        if (mode == 0) {
            if (gcol < SHORTLIST)   bp = weight + (size_t)gcol * KDIM;
            else if (gcol < HEADC)  bp = tailv + (size_t)(gcol - SHORTLIST) * KDIM;
            else                    bp = weight;                  // dup, masked later
        } else {
            int bc = gcol < colhi ? gcol : (colhi - 1);
            bp = weight + (size_t)bc * KDIM;
        }
        bsrc[i] = bp + c * 4;
        bdst[i] = TM * 128 + row * 128 + ((c * 16) ^ ((row & 7) * 16));
    }

    // ---- ldmatrix per-lane address constants
    const int a_rin = (lid & 7) | (((lid >> 3) & 1) << 3);  // A row-in-m16 tile
    const int a_chi = (lid >> 4) & 1;                       // A 16B-chunk hi
    const int b_nin = (lid & 7) | (((lid >> 4) & 1) << 3);  // B class-in-16 group
    const int b_chi = (lid >> 3) & 1;
    const uint32_t xv = (lid & 7) * 16;                     // swizzle XOR

    uint32_t arow_off[4], brow_off[2];
    #pragma unroll
    for (int mi = 0; mi < 4; mi++) arow_off[mi] = (wm * 64 + mi * 16 + a_rin) * 128;
    #pragma unroll
    for (int g = 0; g < 2; g++)    brow_off[g]  = TM * 128 + (wn * 32 + g * 16 + b_nin) * 128;

    // ---- prologue: fill NSTG stages
    #pragma unroll
    for (int s = 0; s < NSTG; s++) {
        uint32_t base = stage0 + s * STAGE_BYTES;
        #pragma unroll
        for (int i = 0; i < 4; i++) CP16(base + adst[i], asrc[i] + s * 32);
        #pragma unroll
        for (int i = 0; i < 4; i++) CP16(base + bdst[i], bsrc[i] + s * 32);
        CP_COMMIT();
    }

    float acc[4][4][4] = {};   // [mi][ni][frag]

    // ---- main loop: 32 K-stages of 32, 4 k8 substeps each
    for (int s = 0; s < 32; s++) {
        uint32_t sbuf = stage0 + (s % NSTG) * STAGE_BYTES;
        if (31 - s >= NSTG - 1)  asm volatile("cp.async.wait_group %0;" :: "n"(NSTG - 1) : "memory");
        else if (31 - s == 1)    asm volatile("cp.async.wait_group 1;" ::: "memory");
        else                     asm volatile("cp.async.wait_group 0;" ::: "memory");
        __syncthreads();

        #pragma unroll
        for (int ks = 0; ks < 4; ks++) {
            uint32_t af[4][4], bf[2][4];
            uint32_t asw = (uint32_t)((ks * 2 + a_chi) * 16) ^ xv;
            uint32_t bsw = (uint32_t)((ks * 2 + b_chi) * 16) ^ xv;
            #pragma unroll
            for (int mi = 0; mi < 4; mi++) LDSM4(af[mi], sbuf + arow_off[mi] + asw);
            #pragma unroll
            for (int g = 0; g < 2; g++)    LDSM4(bf[g],  sbuf + brow_off[g]  + bsw);
            #pragma unroll
            for (int mi = 0; mi < 4; mi++)
                #pragma unroll
                for (int ni = 0; ni < 4; ni++)
                    MMA_TF32(acc[mi][ni], af[mi], bf[ni >> 1][(ni & 1) * 2],
                                                   bf[ni >> 1][(ni & 1) * 2 + 1]);
        }
        __syncthreads();

        if (s + NSTG < 32) {
            int k0 = (s + NSTG) * 32;
            #pragma unroll
            for (int i = 0; i < 4; i++) CP16(sbuf + adst[i], asrc[i] + k0);
            #pragma unroll
            for (int i = 0; i < 4; i++) CP16(sbuf + bdst[i], bsrc[i] + k0);
            CP_COMMIT();
        }
    }

    // ---- epilogue: bias + exp + row-sum + target gather
    float* sumdst = (mode == 0) ? g_head_sum : g_tail_sum;
    float* gatdst = (mode == 0) ? g_head_gath : g_targ_logit;

    #pragma unroll
    for (int mi = 0; mi < 4; mi++) {
        int tr0 = wm * 64 + mi * 16 + (lid >> 2);
        int grow0 = by * TM + tr0, grow1 = grow0 + 8;
        bool v0 = grow0 < nrows, v1 = grow1 < nrows;
        int orow0 = 0, orow1 = 0, gidx0 = -1, gidx1 = -1;
        if (v0) {
            orow0 = rowlist ? rowlist[grow0] : grow0;
            int t = target[orow0];
            gidx0 = (mode == 0) ? ((t < SHORTLIST) ? t : (SHORTLIST + cluster_of(t) - 1)) : t;
        }
        if (v1) {
            orow1 = rowlist ? rowlist[grow1] : grow1;
            int t = target[orow1];
            gidx1 = (mode == 0) ? ((t < SHORTLIST) ? t : (SHORTLIST + cluster_of(t) - 1)) : t;
        }
        float s0 = 0.f, s1 = 0.f, gl0 = 0.f, gl1 = 0.f;
        bool f0 = false, f1 = false;
        #pragma unroll
        for (int ni = 0; ni < 4; ni++) {
            int cbase = wn * 32 + ni * 8 + 2 * (lid & 3);
            #pragma unroll
            for (int h = 0; h < 2; h++) {
                int col = cbase + h;
                int gcol = collo + bx * TN + col;
                if (gcol < colhi) {
                    float bb = bias_sm[col];
                    float l0 = acc[mi][ni][h]     + bb;
                    float l1 = acc[mi][ni][2 + h] + bb;
                    s0 += __expf(l0);
                    s1 += __expf(l1);
                    if (gcol == gidx0) { gl0 = l0; f0 = true; }
                    if (gcol == gidx1) { gl1 = l1; f1 = true; }
                }
            }
        }
        // reduce across the 4 lanes sharing each row
        s0 += __shfl_xor_sync(0xffffffffu, s0, 1);
        s0 += __shfl_xor_sync(0xffffffffu, s0, 2);
        s1 += __shfl_xor_sync(0xffffffffu, s1, 1);
        s1 += __shfl_xor_sync(0xffffffffu, s1, 2);
        if ((lid & 3) == 0) {
            if (v0) atomicAdd(&sumdst[orow0], s0);
            if (v1) atomicAdd(&sumdst[orow1], s1);
        }
        if (f0 && v0) gatdst[orow0] = gl0;
        if (f1 && v1) gatdst[orow1] = gl1;
    }
}

// ---------------- finalize ----------------------------------------------------
__global__ void finalize_kernel(const int* __restrict__ target,
                                float* __restrict__ out)
{
    __shared__ float red[256];
    int i = blockIdx.x * 256 + threadIdx.x;
    float neg = 0.f;
    if (i < NROWS) {
        int cid = cluster_of(target[i]);
        float res = g_head_gath[i] - logf(g_head_sum[i]);
        if (cid > 0) res += g_targ_logit[i] - logf(g_tail_sum[i]);
        out[i] = res;
        neg = -res;
    }
    red[threadIdx.x] = neg;
    __syncthreads();
    #pragma unroll
    for (int s2 = 128; s2 > 0; s2 >>= 1) {
        if (threadIdx.x < s2) red[threadIdx.x] += red[threadIdx.x + s2];
        __syncthreads();
    }
    if (threadIdx.x == 0) atomicAdd(&g_loss, red[0]);
}
__global__ void write_loss_kernel(float* __restrict__ out, int out_size) {
    if (out_size > NROWS) out[NROWS] = g_loss / (float)NROWS;
}

// ---------------- launch ------------------------------------------------------
extern "C" void kernel_launch(void* const* d_in, const int* in_sizes, int n_in,
                              void* d_out, int out_size) {
    const float* input  = (const float*)d_in[0];
    const int*   target = (const int*)  d_in[1];
    const float* weight = (const float*)d_in[2];
    const float* bias   = (const float*)d_in[3];
    const float* tailv  = (const float*)d_in[4];
    const float* tailb  = (const float*)d_in[5];
    float* out = (float*)d_out;

    cudaFuncSetAttribute(tc_gemm_lse, cudaFuncAttributeMaxDynamicSharedMemorySize, SMEM_TOTAL);

    init_kernel<<<NROWS / 256, 256>>>();
    compact_kernel<<<NROWS / 256, 256>>>(target);

    tc_gemm_lse<<<dim3(NROWS / TM, (HEADC + TN - 1) / TN), 256, SMEM_TOTAL>>>(
        input, target, weight, bias, tailv, tailb, 0);
    tc_gemm_lse<<<dim3(NROWS / TM, (C1HI - SHORTLIST) / TN), 256, SMEM_TOTAL>>>(
        input, target, weight, bias, tailv, tailb, 1);
    tc_gemm_lse<<<dim3(NROWS / TM, (NCLASSES - C1HI + TN - 1) / TN), 256, SMEM_TOTAL>>>(
        input, target, weight, bias, tailv, tailb, 2);

    finalize_kernel<<<NROWS / 256, 256>>>(target, out);
    write_loss_kernel<<<1, 1>>>(out, out_size);
}